// round 6
// baseline (speedup 1.0000x reference)
#include <cuda_runtime.h>
#include <math.h>

#define NN 100000
#define DD 128
#define HH 64
#define CC 40
#define NB 391          // ceil(NN/256) scan blocks

typedef unsigned long long u64;

// ---- scratch (__device__ globals per harness rules) ----
__device__ float g_y1[(size_t)NN * HH];     // x @ W1l            25.6 MB
__device__ float g_self[(size_t)NN * HH];   // x @ W1r + b1       25.6 MB
__device__ float g_h[(size_t)NN * HH];      // layer-1 output     25.6 MB
__device__ float g_agg2[(size_t)NN * HH];   // mean(h[nbrs])      25.6 MB
__device__ int   g_cnt[NN];
__device__ int   g_rowptr[NN];
__device__ int   g_cur[NN];
__device__ float g_invdeg[NN];
__device__ int   g_srcs[2000000];
__device__ int   g_exc[NB * 256];
__device__ int   g_bsum[512];
__device__ int   g_is64;

// ---- f32x2 packed-math helpers (sm_103a FFMA2) ----
__device__ __forceinline__ u64 pack2(float lo, float hi) {
    u64 r;
    asm("mov.b64 %0, {%1, %2};" : "=l"(r) : "f"(lo), "f"(hi));
    return r;
}
__device__ __forceinline__ void unpack2(u64 v, float& lo, float& hi) {
    asm("mov.b64 {%0, %1}, %2;" : "=f"(lo), "=f"(hi) : "l"(v));
}
__device__ __forceinline__ void fma2(u64& d, u64 a, u64 b) {
    asm("fma.rn.f32x2 %0, %1, %2, %0;" : "+l"(d) : "l"(a), "l"(b));
}

// ---------------------------------------------------------------------------
// detzero: zero g_cnt everywhere; block 0 also detects int64 vs int32 edge
// dtype in parallel (128 lanes + ballot instead of 1 serial thread).
// ---------------------------------------------------------------------------
__global__ void k_detzero(const void* __restrict__ ei) {
    int i = blockIdx.x * blockDim.x + threadIdx.x;
    if (i < NN) g_cnt[i] = 0;
    if (blockIdx.x == 0 && threadIdx.x < 128) {
        long long v = ((const long long*)ei)[threadIdx.x];
        bool bad = (v < 0 || v >= NN);
        unsigned m = __ballot_sync(0xffffffffu, bad);
        if ((threadIdx.x & 31) == 0) {
            if (m) atomicExch(&g_is64, 0);
            else if (threadIdx.x == 0) { /* provisional */ }
        }
        if (threadIdx.x == 0) g_is64 = 1;   // set first...
        __syncthreads();
        // redo robustly: all 128 lanes vote through shared
        __shared__ int anybad;
        if (threadIdx.x == 0) anybad = 0;
        __syncthreads();
        if (bad) anybad = 1;
        __syncthreads();
        if (threadIdx.x == 0) g_is64 = anybad ? 0 : 1;
    }
}

__global__ void k_hist(const void* __restrict__ ei, int nE) {
    int e = blockIdx.x * blockDim.x + threadIdx.x;
    if (e >= nE) return;
    int d = g_is64 ? (int)((const long long*)ei)[nE + e]
                   : ((const int*)ei)[nE + e];
    atomicAdd(&g_cnt[d], 1);
}

__global__ void k_scan1() {
    __shared__ int sh[256];
    int t = threadIdx.x, b = blockIdx.x;
    int i = b * 256 + t;
    int v = (i < NN) ? g_cnt[i] : 0;
    sh[t] = v;
    __syncthreads();
    #pragma unroll
    for (int off = 1; off < 256; off <<= 1) {
        int u = (t >= off) ? sh[t - off] : 0;
        __syncthreads();
        sh[t] += u;
        __syncthreads();
    }
    if (i < NN) g_exc[i] = sh[t] - v;
    if (t == 255) g_bsum[b] = sh[t];
}

// ---------------------------------------------------------------------------
// scan23: each block b re-reduces g_bsum[0..b-1] (<=391 ints, trivially cheap)
// then finalizes rowptr / cur / invdeg for its 256 nodes. Saves one launch.
// ---------------------------------------------------------------------------
__global__ void k_scan23() {
    __shared__ int red[8];
    __shared__ int boff;
    int b = blockIdx.x, t = threadIdx.x;
    int v = 0;
    if (t < b) v = g_bsum[t];
    if (t + 256 < b) v += g_bsum[t + 256];
    #pragma unroll
    for (int o = 16; o; o >>= 1) v += __shfl_xor_sync(0xffffffffu, v, o);
    if ((t & 31) == 0) red[t >> 5] = v;
    __syncthreads();
    if (t == 0) {
        int s = 0;
        #pragma unroll
        for (int j = 0; j < 8; ++j) s += red[j];
        boff = s;
    }
    __syncthreads();
    int i = b * 256 + t;
    if (i < NN) {
        int row = g_exc[i] + boff;
        g_rowptr[i] = row;
        g_cur[i] = row;
        g_invdeg[i] = 1.0f / fmaxf((float)g_cnt[i], 1.0f);
    }
}

__global__ void k_fill(const void* __restrict__ ei, int nE) {
    int e = blockIdx.x * blockDim.x + threadIdx.x;
    if (e >= nE) return;
    int s, d;
    if (g_is64) {
        const long long* p = (const long long*)ei;
        s = (int)p[e]; d = (int)p[nE + e];
    } else {
        const int* p = (const int*)ei;
        s = p[e]; d = p[nE + e];
    }
    int pos = atomicAdd(&g_cur[d], 1);
    g_srcs[pos] = s;
}

// ---------------------------------------------------------------------------
// GEMM1: [y1 | self+b1] = x[N,128] @ [W1l | W1r][128,128]
// 64x128 tile, 256 threads, 4x8 microtile in packed f32x2 FMA.
// ---------------------------------------------------------------------------
__global__ void k_gemm1(const float* __restrict__ x,
                        const float* __restrict__ Wl,
                        const float* __restrict__ Wr,
                        const float* __restrict__ b) {
    __shared__ float As[32][65];
    __shared__ float Bs[32][128];

    int tid = threadIdx.x;
    int tx = tid & 15;
    int ty = tid >> 4;
    int m0 = blockIdx.x * 64;

    u64 acc[4][4] = {};

    #pragma unroll 1
    for (int c = 0; c < 4; ++c) {
        int kb = c * 32;
        __syncthreads();
        {
            int kk = (tid & 7) * 4;
            int m  = tid >> 3;
            #pragma unroll
            for (int r = 0; r < 2; ++r, m += 32) {
                int mg = min(m0 + m, NN - 1);
                float4 v = __ldg((const float4*)(x + (size_t)mg * DD + kb + kk));
                As[kk + 0][m] = v.x;
                As[kk + 1][m] = v.y;
                As[kk + 2][m] = v.z;
                As[kk + 3][m] = v.w;
            }
        }
        {
            int k = tid >> 3;
            int n = (tid & 7) * 16;
            const float* W = (n < 64) ? (Wl + (size_t)(kb + k) * 64 + n)
                                      : (Wr + (size_t)(kb + k) * 64 + (n - 64));
            float4 v0 = __ldg((const float4*)(W));
            float4 v1 = __ldg((const float4*)(W + 4));
            float4 v2 = __ldg((const float4*)(W + 8));
            float4 v3 = __ldg((const float4*)(W + 12));
            *(float4*)&Bs[k][n]      = v0;
            *(float4*)&Bs[k][n + 4]  = v1;
            *(float4*)&Bs[k][n + 8]  = v2;
            *(float4*)&Bs[k][n + 12] = v3;
        }
        __syncthreads();
        #pragma unroll
        for (int k = 0; k < 32; ++k) {
            u64 A2[4];
            #pragma unroll
            for (int i = 0; i < 4; ++i) {
                float a = As[k][ty * 4 + i];
                A2[i] = pack2(a, a);
            }
            const u64* bp = (const u64*)&Bs[k][tx * 8];
            u64 B0 = bp[0], B1 = bp[1], B2 = bp[2], B3 = bp[3];
            #pragma unroll
            for (int i = 0; i < 4; ++i) {
                fma2(acc[i][0], A2[i], B0);
                fma2(acc[i][1], A2[i], B1);
                fma2(acc[i][2], A2[i], B2);
                fma2(acc[i][3], A2[i], B3);
            }
        }
    }

    int n = tx * 8;
    bool isSelf = (n >= 64);
    float bb[8];
    #pragma unroll
    for (int j = 0; j < 8; ++j) bb[j] = isSelf ? b[n - 64 + j] : 0.f;
    float* dst = isSelf ? g_self : g_y1;
    int nc = isSelf ? (n - 64) : n;
    #pragma unroll
    for (int i = 0; i < 4; ++i) {
        int mg = m0 + ty * 4 + i;
        if (mg < NN) {
            float o[8];
            #pragma unroll
            for (int j = 0; j < 4; ++j) unpack2(acc[i][j], o[2 * j], o[2 * j + 1]);
            float4 o0, o1;
            o0.x = o[0] + bb[0]; o0.y = o[1] + bb[1];
            o0.z = o[2] + bb[2]; o0.w = o[3] + bb[3];
            o1.x = o[4] + bb[4]; o1.y = o[5] + bb[5];
            o1.z = o[6] + bb[6]; o1.w = o[7] + bb[7];
            *(float4*)(dst + (size_t)mg * HH + nc)     = o0;
            *(float4*)(dst + (size_t)mg * HH + nc + 4) = o1;
        }
    }
}

// ---------------------------------------------------------------------------
// agg1 + ReLU: h[n] = relu( invdeg * sum_{s} y1[s] + self[n] )
// warp per node, lane -> float2. Cooperative src prefetch (1 coalesced LDG
// per 32 edges) + 4 independent gathers in flight (MLP=4).
// ---------------------------------------------------------------------------
__global__ void k_agg1(void) {
    int w = (blockIdx.x * blockDim.x + threadIdx.x) >> 5;
    int lane = threadIdx.x & 31;
    if (w >= NN) return;
    int beg = g_rowptr[w], n = g_cnt[w];
    const float2* yb = (const float2*)g_y1;
    float2 A0 = {0.f,0.f}, A1 = {0.f,0.f}, A2 = {0.f,0.f}, A3 = {0.f,0.f};

    for (int base = 0; base < n; base += 32) {
        int cnt = min(n - base, 32);
        int sidx = (lane < cnt) ? g_srcs[beg + base + lane] : 0;
        int j = 0;
        for (; j + 4 <= cnt; j += 4) {
            int s0 = __shfl_sync(0xffffffffu, sidx, j);
            int s1 = __shfl_sync(0xffffffffu, sidx, j + 1);
            int s2 = __shfl_sync(0xffffffffu, sidx, j + 2);
            int s3 = __shfl_sync(0xffffffffu, sidx, j + 3);
            float2 v0 = __ldg(yb + (size_t)s0 * 32 + lane);
            float2 v1 = __ldg(yb + (size_t)s1 * 32 + lane);
            float2 v2 = __ldg(yb + (size_t)s2 * 32 + lane);
            float2 v3 = __ldg(yb + (size_t)s3 * 32 + lane);
            A0.x += v0.x; A0.y += v0.y;
            A1.x += v1.x; A1.y += v1.y;
            A2.x += v2.x; A2.y += v2.y;
            A3.x += v3.x; A3.y += v3.y;
        }
        for (; j < cnt; ++j) {
            int s0 = __shfl_sync(0xffffffffu, sidx, j);
            float2 v0 = __ldg(yb + (size_t)s0 * 32 + lane);
            A0.x += v0.x; A0.y += v0.y;
        }
    }
    float sc = g_invdeg[w];
    float2 s = ((const float2*)g_self)[(size_t)w * 32 + lane];
    float2 o;
    o.x = fmaxf((A0.x + A1.x + A2.x + A3.x) * sc + s.x, 0.f);
    o.y = fmaxf((A0.y + A1.y + A2.y + A3.y) * sc + s.y, 0.f);
    ((float2*)g_h)[(size_t)w * 32 + lane] = o;
}

// ---------------------------------------------------------------------------
// agg2: g_agg2[n] = invdeg * sum_{s} h[s]   (same gather scheme)
// ---------------------------------------------------------------------------
__global__ void k_agg2(void) {
    int w = (blockIdx.x * blockDim.x + threadIdx.x) >> 5;
    int lane = threadIdx.x & 31;
    if (w >= NN) return;
    int beg = g_rowptr[w], n = g_cnt[w];
    const float2* hb = (const float2*)g_h;
    float2 A0 = {0.f,0.f}, A1 = {0.f,0.f}, A2 = {0.f,0.f}, A3 = {0.f,0.f};

    for (int base = 0; base < n; base += 32) {
        int cnt = min(n - base, 32);
        int sidx = (lane < cnt) ? g_srcs[beg + base + lane] : 0;
        int j = 0;
        for (; j + 4 <= cnt; j += 4) {
            int s0 = __shfl_sync(0xffffffffu, sidx, j);
            int s1 = __shfl_sync(0xffffffffu, sidx, j + 1);
            int s2 = __shfl_sync(0xffffffffu, sidx, j + 2);
            int s3 = __shfl_sync(0xffffffffu, sidx, j + 3);
            float2 v0 = __ldg(hb + (size_t)s0 * 32 + lane);
            float2 v1 = __ldg(hb + (size_t)s1 * 32 + lane);
            float2 v2 = __ldg(hb + (size_t)s2 * 32 + lane);
            float2 v3 = __ldg(hb + (size_t)s3 * 32 + lane);
            A0.x += v0.x; A0.y += v0.y;
            A1.x += v1.x; A1.y += v1.y;
            A2.x += v2.x; A2.y += v2.y;
            A3.x += v3.x; A3.y += v3.y;
        }
        for (; j < cnt; ++j) {
            int s0 = __shfl_sync(0xffffffffu, sidx, j);
            float2 v0 = __ldg(hb + (size_t)s0 * 32 + lane);
            A0.x += v0.x; A0.y += v0.y;
        }
    }
    float sc = g_invdeg[w];
    float2 o;
    o.x = (A0.x + A1.x + A2.x + A3.x) * sc;
    o.y = (A0.y + A1.y + A2.y + A3.y) * sc;
    ((float2*)g_agg2)[(size_t)w * 32 + lane] = o;
}

// ---------------------------------------------------------------------------
// GEMM2 + fused log_softmax (warp per node), packed f32x2.
// ---------------------------------------------------------------------------
__global__ void k_gemm2(const float* __restrict__ Wl,
                        const float* __restrict__ Wr,
                        const float* __restrict__ b,
                        float* __restrict__ out) {
    __shared__ float2 sW[64 * 40];
    __shared__ float sb[40];
    int tid = threadIdx.x;
    for (int i = tid; i < 64 * 40; i += blockDim.x)
        sW[i] = make_float2(Wl[i], Wr[i]);
    if (tid < 40) sb[tid] = b[tid];
    __syncthreads();

    int w = (blockIdx.x * blockDim.x + tid) >> 5;
    int lane = tid & 31;
    if (w >= NN) return;
    bool lo8 = (lane < 8);

    const float* ag = g_agg2 + (size_t)w * HH;
    const float* hr = g_h    + (size_t)w * HH;
    float a0 = ag[lane], a1 = ag[lane + 32];
    float h0 = hr[lane], h1 = hr[lane + 32];

    u64 acc0 = 0, acc1 = 0;
    #pragma unroll
    for (int k = 0; k < 32; ++k) {
        float av = __shfl_sync(0xffffffffu, a0, k);
        float hv = __shfl_sync(0xffffffffu, h0, k);
        u64 p = pack2(av, hv);
        fma2(acc0, p, *(const u64*)&sW[k * 40 + lane]);
        if (lo8) fma2(acc1, p, *(const u64*)&sW[k * 40 + 32 + lane]);
    }
    #pragma unroll
    for (int k = 0; k < 32; ++k) {
        float av = __shfl_sync(0xffffffffu, a1, k);
        float hv = __shfl_sync(0xffffffffu, h1, k);
        u64 p = pack2(av, hv);
        int kr = k + 32;
        fma2(acc0, p, *(const u64*)&sW[kr * 40 + lane]);
        if (lo8) fma2(acc1, p, *(const u64*)&sW[kr * 40 + 32 + lane]);
    }

    float u0, v0, u1, v1;
    unpack2(acc0, u0, v0);
    unpack2(acc1, u1, v1);
    float z0 = u0 + v0 + sb[lane];
    float z1 = lo8 ? (u1 + v1 + sb[32 + lane]) : -INFINITY;

    float m = fmaxf(z0, z1);
    #pragma unroll
    for (int o = 16; o; o >>= 1) m = fmaxf(m, __shfl_xor_sync(0xffffffffu, m, o));
    float e = expf(z0 - m) + (lo8 ? expf(z1 - m) : 0.f);
    #pragma unroll
    for (int o = 16; o; o >>= 1) e += __shfl_xor_sync(0xffffffffu, e, o);
    float lse = logf(e) + m;

    out[(size_t)w * CC + lane] = z0 - lse;
    if (lo8) out[(size_t)w * CC + 32 + lane] = z1 - lse;
}

// ---------------------------------------------------------------------------
extern "C" void kernel_launch(void* const* d_in, const int* in_sizes, int n_in,
                              void* d_out, int out_size) {
    const float* x   = (const float*)d_in[0];
    const void*  ei  = d_in[1];
    const float* W1l = (const float*)d_in[2];
    const float* W1r = (const float*)d_in[3];
    const float* b1  = (const float*)d_in[4];
    const float* W2l = (const float*)d_in[5];
    const float* W2r = (const float*)d_in[6];
    const float* b2  = (const float*)d_in[7];
    float* out = (float*)d_out;

    int nE = in_sizes[1] / 2;
    int eBlocks = (nE + 255) / 256;
    int nWarpBlocks = (NN * 32 + 255) / 256;

    k_detzero<<<(NN + 255) / 256, 256>>>(ei);        // 1
    k_hist<<<eBlocks, 256>>>(ei, nE);                // 2
    k_scan1<<<NB, 256>>>();                          // 3
    k_scan23<<<NB, 256>>>();                         // 4
    k_fill<<<eBlocks, 256>>>(ei, nE);                // 5
    k_gemm1<<<(NN + 63) / 64, 256>>>(x, W1l, W1r, b1); // 6 <- ncu window
    k_agg1<<<nWarpBlocks, 256>>>();                  // 7
    k_agg2<<<nWarpBlocks, 256>>>();                  // 8
    k_gemm2<<<(NN + 7) / 8, 256>>>(W2l, W2r, b2, out); // 9
}

// round 7
// speedup vs baseline: 1.0434x; 1.0434x over previous
#include <cuda_runtime.h>
#include <math.h>

#define NN 100000
#define DD 128
#define HH 64
#define CC 40
#define NB 391          // ceil(NN/256) scan blocks

typedef unsigned long long u64;

// ---- scratch (__device__ globals per harness rules) ----
__device__ float g_y1[(size_t)NN * HH];     // x @ W1l            25.6 MB
__device__ float g_self[(size_t)NN * HH];   // x @ W1r + b1       25.6 MB
__device__ float g_h[(size_t)NN * HH];      // layer-1 output     25.6 MB
__device__ float g_agg2[(size_t)NN * HH];   // mean(h[nbrs])      25.6 MB
__device__ int   g_cnt[NN];
__device__ int   g_rowptr[NN];
__device__ int   g_cur[NN];
__device__ float g_invdeg[NN];
__device__ int   g_srcs[2000000];
__device__ int   g_exc[NB * 256];
__device__ int   g_bsum[512];
__device__ int   g_is64;

// ---- f32x2 packed-math helpers (sm_103a FFMA2) ----
__device__ __forceinline__ u64 pack2(float lo, float hi) {
    u64 r;
    asm("mov.b64 %0, {%1, %2};" : "=l"(r) : "f"(lo), "f"(hi));
    return r;
}
__device__ __forceinline__ void unpack2(u64 v, float& lo, float& hi) {
    asm("mov.b64 {%0, %1}, %2;" : "=f"(lo), "=f"(hi) : "l"(v));
}
__device__ __forceinline__ void fma2(u64& d, u64 a, u64 b) {
    asm("fma.rn.f32x2 %0, %1, %2, %0;" : "+l"(d) : "l"(a), "l"(b));
}

// ---------------------------------------------------------------------------
// detzero: zero g_cnt; block 0 detects int64 vs int32 edge dtype in parallel.
// ---------------------------------------------------------------------------
__global__ void k_detzero(const void* __restrict__ ei) {
    int i = blockIdx.x * blockDim.x + threadIdx.x;
    if (i < NN) g_cnt[i] = 0;
    if (blockIdx.x == 0) {
        if (threadIdx.x == 0) g_is64 = 1;
        __syncthreads();
        if (threadIdx.x < 128) {
            long long v = ((const long long*)ei)[threadIdx.x];
            if (v < 0 || v >= NN) atomicAnd(&g_is64, 0);
        }
    }
}

__global__ void k_hist(const void* __restrict__ ei, int nE) {
    int e = blockIdx.x * blockDim.x + threadIdx.x;
    if (e >= nE) return;
    int d = g_is64 ? (int)((const long long*)ei)[nE + e]
                   : ((const int*)ei)[nE + e];
    atomicAdd(&g_cnt[d], 1);
}

__global__ void k_scan1() {
    __shared__ int sh[256];
    int t = threadIdx.x, b = blockIdx.x;
    int i = b * 256 + t;
    int v = (i < NN) ? g_cnt[i] : 0;
    sh[t] = v;
    __syncthreads();
    #pragma unroll
    for (int off = 1; off < 256; off <<= 1) {
        int u = (t >= off) ? sh[t - off] : 0;
        __syncthreads();
        sh[t] += u;
        __syncthreads();
    }
    if (i < NN) g_exc[i] = sh[t] - v;
    if (t == 255) g_bsum[b] = sh[t];
}

// ---------------------------------------------------------------------------
// scan23: each block b re-reduces g_bsum[0..b-1] then finalizes rowptr/cur/
// invdeg for its 256 nodes.
// ---------------------------------------------------------------------------
__global__ void k_scan23() {
    __shared__ int red[8];
    __shared__ int boff;
    int b = blockIdx.x, t = threadIdx.x;
    int v = 0;
    if (t < b) v = g_bsum[t];
    if (t + 256 < b) v += g_bsum[t + 256];
    #pragma unroll
    for (int o = 16; o; o >>= 1) v += __shfl_xor_sync(0xffffffffu, v, o);
    if ((t & 31) == 0) red[t >> 5] = v;
    __syncthreads();
    if (t == 0) {
        int s = 0;
        #pragma unroll
        for (int j = 0; j < 8; ++j) s += red[j];
        boff = s;
    }
    __syncthreads();
    int i = b * 256 + t;
    if (i < NN) {
        int row = g_exc[i] + boff;
        g_rowptr[i] = row;
        g_cur[i] = row;
        g_invdeg[i] = 1.0f / fmaxf((float)g_cnt[i], 1.0f);
    }
}

__global__ void k_fill(const void* __restrict__ ei, int nE) {
    int e = blockIdx.x * blockDim.x + threadIdx.x;
    if (e >= nE) return;
    int s, d;
    if (g_is64) {
        const long long* p = (const long long*)ei;
        s = (int)p[e]; d = (int)p[nE + e];
    } else {
        const int* p = (const int*)ei;
        s = p[e]; d = p[nE + e];
    }
    int pos = atomicAdd(&g_cur[d], 1);
    g_srcs[pos] = s;
}

// ---------------------------------------------------------------------------
// GEMM1: [y1 | self+b1] = x[N,128] @ [W1l | W1r][128,128]
// 64x128 tile, 256 threads, 4x8 microtile in packed f32x2 FMA.
// ---------------------------------------------------------------------------
__global__ void k_gemm1(const float* __restrict__ x,
                        const float* __restrict__ Wl,
                        const float* __restrict__ Wr,
                        const float* __restrict__ b) {
    __shared__ float As[32][65];
    __shared__ float Bs[32][128];

    int tid = threadIdx.x;
    int tx = tid & 15;
    int ty = tid >> 4;
    int m0 = blockIdx.x * 64;

    u64 acc[4][4] = {};

    #pragma unroll 1
    for (int c = 0; c < 4; ++c) {
        int kb = c * 32;
        __syncthreads();
        {
            int kk = (tid & 7) * 4;
            int m  = tid >> 3;
            #pragma unroll
            for (int r = 0; r < 2; ++r, m += 32) {
                int mg = min(m0 + m, NN - 1);
                float4 v = __ldg((const float4*)(x + (size_t)mg * DD + kb + kk));
                As[kk + 0][m] = v.x;
                As[kk + 1][m] = v.y;
                As[kk + 2][m] = v.z;
                As[kk + 3][m] = v.w;
            }
        }
        {
            int k = tid >> 3;
            int n = (tid & 7) * 16;
            const float* W = (n < 64) ? (Wl + (size_t)(kb + k) * 64 + n)
                                      : (Wr + (size_t)(kb + k) * 64 + (n - 64));
            float4 v0 = __ldg((const float4*)(W));
            float4 v1 = __ldg((const float4*)(W + 4));
            float4 v2 = __ldg((const float4*)(W + 8));
            float4 v3 = __ldg((const float4*)(W + 12));
            *(float4*)&Bs[k][n]      = v0;
            *(float4*)&Bs[k][n + 4]  = v1;
            *(float4*)&Bs[k][n + 8]  = v2;
            *(float4*)&Bs[k][n + 12] = v3;
        }
        __syncthreads();
        #pragma unroll
        for (int k = 0; k < 32; ++k) {
            u64 A2[4];
            #pragma unroll
            for (int i = 0; i < 4; ++i) {
                float a = As[k][ty * 4 + i];
                A2[i] = pack2(a, a);
            }
            const u64* bp = (const u64*)&Bs[k][tx * 8];
            u64 B0 = bp[0], B1 = bp[1], B2 = bp[2], B3 = bp[3];
            #pragma unroll
            for (int i = 0; i < 4; ++i) {
                fma2(acc[i][0], A2[i], B0);
                fma2(acc[i][1], A2[i], B1);
                fma2(acc[i][2], A2[i], B2);
                fma2(acc[i][3], A2[i], B3);
            }
        }
    }

    int n = tx * 8;
    bool isSelf = (n >= 64);
    float bb[8];
    #pragma unroll
    for (int j = 0; j < 8; ++j) bb[j] = isSelf ? b[n - 64 + j] : 0.f;
    float* dst = isSelf ? g_self : g_y1;
    int nc = isSelf ? (n - 64) : n;
    #pragma unroll
    for (int i = 0; i < 4; ++i) {
        int mg = m0 + ty * 4 + i;
        if (mg < NN) {
            float o[8];
            #pragma unroll
            for (int j = 0; j < 4; ++j) unpack2(acc[i][j], o[2 * j], o[2 * j + 1]);
            float4 o0, o1;
            o0.x = o[0] + bb[0]; o0.y = o[1] + bb[1];
            o0.z = o[2] + bb[2]; o0.w = o[3] + bb[3];
            o1.x = o[4] + bb[4]; o1.y = o[5] + bb[5];
            o1.z = o[6] + bb[6]; o1.w = o[7] + bb[7];
            *(float4*)(dst + (size_t)mg * HH + nc)     = o0;
            *(float4*)(dst + (size_t)mg * HH + nc + 4) = o1;
        }
    }
}

// ---------------------------------------------------------------------------
// agg1 + ReLU: h[n] = relu( invdeg * sum_{s} y1[s] + self[n] )
// warp per node, lane -> float2, 2 independent gathers in flight.
// ---------------------------------------------------------------------------
__global__ void k_agg1(void) {
    int w = (blockIdx.x * blockDim.x + threadIdx.x) >> 5;
    int lane = threadIdx.x & 31;
    if (w >= NN) return;
    int beg = g_rowptr[w], n = g_cnt[w];
    const float2* yb = (const float2*)g_y1;
    float2 a0 = make_float2(0.f, 0.f), a1 = make_float2(0.f, 0.f);
    int e = 0;
    for (; e + 1 < n; e += 2) {
        int s0 = g_srcs[beg + e];
        int s1 = g_srcs[beg + e + 1];
        float2 v0 = __ldg(yb + (size_t)s0 * 32 + lane);
        float2 v1 = __ldg(yb + (size_t)s1 * 32 + lane);
        a0.x += v0.x; a0.y += v0.y;
        a1.x += v1.x; a1.y += v1.y;
    }
    if (e < n) {
        int s0 = g_srcs[beg + e];
        float2 v0 = __ldg(yb + (size_t)s0 * 32 + lane);
        a0.x += v0.x; a0.y += v0.y;
    }
    float sc = g_invdeg[w];
    float2 s = ((const float2*)g_self)[(size_t)w * 32 + lane];
    float2 o;
    o.x = fmaxf((a0.x + a1.x) * sc + s.x, 0.f);
    o.y = fmaxf((a0.y + a1.y) * sc + s.y, 0.f);
    ((float2*)g_h)[(size_t)w * 32 + lane] = o;
}

// ---------------------------------------------------------------------------
// agg2: g_agg2[n] = invdeg * sum_{s} h[s]
// ---------------------------------------------------------------------------
__global__ void k_agg2(void) {
    int w = (blockIdx.x * blockDim.x + threadIdx.x) >> 5;
    int lane = threadIdx.x & 31;
    if (w >= NN) return;
    int beg = g_rowptr[w], n = g_cnt[w];
    const float2* hb = (const float2*)g_h;
    float2 a0 = make_float2(0.f, 0.f), a1 = make_float2(0.f, 0.f);
    int e = 0;
    for (; e + 1 < n; e += 2) {
        int s0 = g_srcs[beg + e];
        int s1 = g_srcs[beg + e + 1];
        float2 v0 = __ldg(hb + (size_t)s0 * 32 + lane);
        float2 v1 = __ldg(hb + (size_t)s1 * 32 + lane);
        a0.x += v0.x; a0.y += v0.y;
        a1.x += v1.x; a1.y += v1.y;
    }
    if (e < n) {
        int s0 = g_srcs[beg + e];
        float2 v0 = __ldg(hb + (size_t)s0 * 32 + lane);
        a0.x += v0.x; a0.y += v0.y;
    }
    float sc = g_invdeg[w];
    float2 o;
    o.x = (a0.x + a1.x) * sc;
    o.y = (a0.y + a1.y) * sc;
    ((float2*)g_agg2)[(size_t)w * 32 + lane] = o;
}

// ---------------------------------------------------------------------------
// GEMM2 + fused log_softmax (warp per node), packed f32x2.
// ---------------------------------------------------------------------------
__global__ void k_gemm2(const float* __restrict__ Wl,
                        const float* __restrict__ Wr,
                        const float* __restrict__ b,
                        float* __restrict__ out) {
    __shared__ float2 sW[64 * 40];
    __shared__ float sb[40];
    int tid = threadIdx.x;
    for (int i = tid; i < 64 * 40; i += blockDim.x)
        sW[i] = make_float2(Wl[i], Wr[i]);
    if (tid < 40) sb[tid] = b[tid];
    __syncthreads();

    int w = (blockIdx.x * blockDim.x + tid) >> 5;
    int lane = tid & 31;
    if (w >= NN) return;
    bool lo8 = (lane < 8);

    const float* ag = g_agg2 + (size_t)w * HH;
    const float* hr = g_h    + (size_t)w * HH;
    float a0 = ag[lane], a1 = ag[lane + 32];
    float h0 = hr[lane], h1 = hr[lane + 32];

    u64 acc0 = 0, acc1 = 0;
    #pragma unroll
    for (int k = 0; k < 32; ++k) {
        float av = __shfl_sync(0xffffffffu, a0, k);
        float hv = __shfl_sync(0xffffffffu, h0, k);
        u64 p = pack2(av, hv);
        fma2(acc0, p, *(const u64*)&sW[k * 40 + lane]);
        if (lo8) fma2(acc1, p, *(const u64*)&sW[k * 40 + 32 + lane]);
    }
    #pragma unroll
    for (int k = 0; k < 32; ++k) {
        float av = __shfl_sync(0xffffffffu, a1, k);
        float hv = __shfl_sync(0xffffffffu, h1, k);
        u64 p = pack2(av, hv);
        int kr = k + 32;
        fma2(acc0, p, *(const u64*)&sW[kr * 40 + lane]);
        if (lo8) fma2(acc1, p, *(const u64*)&sW[kr * 40 + 32 + lane]);
    }

    float u0, v0, u1, v1;
    unpack2(acc0, u0, v0);
    unpack2(acc1, u1, v1);
    float z0 = u0 + v0 + sb[lane];
    float z1 = lo8 ? (u1 + v1 + sb[32 + lane]) : -INFINITY;

    float m = fmaxf(z0, z1);
    #pragma unroll
    for (int o = 16; o; o >>= 1) m = fmaxf(m, __shfl_xor_sync(0xffffffffu, m, o));
    float e = expf(z0 - m) + (lo8 ? expf(z1 - m) : 0.f);
    #pragma unroll
    for (int o = 16; o; o >>= 1) e += __shfl_xor_sync(0xffffffffu, e, o);
    float lse = logf(e) + m;

    out[(size_t)w * CC + lane] = z0 - lse;
    if (lo8) out[(size_t)w * CC + 32 + lane] = z1 - lse;
}

// ---------------------------------------------------------------------------
extern "C" void kernel_launch(void* const* d_in, const int* in_sizes, int n_in,
                              void* d_out, int out_size) {
    const float* x   = (const float*)d_in[0];
    const void*  ei  = d_in[1];
    const float* W1l = (const float*)d_in[2];
    const float* W1r = (const float*)d_in[3];
    const float* b1  = (const float*)d_in[4];
    const float* W2l = (const float*)d_in[5];
    const float* W2r = (const float*)d_in[6];
    const float* b2  = (const float*)d_in[7];
    float* out = (float*)d_out;

    int nE = in_sizes[1] / 2;
    int eBlocks = (nE + 255) / 256;
    int nWarpBlocks = (NN * 32 + 255) / 256;

    // gemm1 has no CSR dependency -> launch 4th so it lands in the ncu window
    k_detzero<<<(NN + 255) / 256, 256>>>(ei);          // 1
    k_hist<<<eBlocks, 256>>>(ei, nE);                  // 2
    k_scan1<<<NB, 256>>>();                            // 3
    k_gemm1<<<(NN + 63) / 64, 256>>>(x, W1l, W1r, b1); // 4 <- ncu window
    k_scan23<<<NB, 256>>>();                           // 5
    k_fill<<<eBlocks, 256>>>(ei, nE);                  // 6
    k_agg1<<<nWarpBlocks, 256>>>();                    // 7
    k_agg2<<<nWarpBlocks, 256>>>();                    // 8
    k_gemm2<<<(NN + 7) / 8, 256>>>(W2l, W2r, b2, out); // 9
}

// round 8
// speedup vs baseline: 1.0538x; 1.0099x over previous
#include <cuda_runtime.h>
#include <math.h>

#define NN 100000
#define DD 128
#define HH 64
#define CC 40
#define NB 391          // ceil(NN/256) scan blocks

typedef unsigned long long u64;

// ---- scratch (__device__ globals per harness rules) ----
__device__ float g_y1[(size_t)NN * HH];     // x @ W1l            25.6 MB
__device__ float g_self[(size_t)NN * HH];   // x @ W1r + b1       25.6 MB
__device__ float g_h[(size_t)NN * HH];      // layer-1 output     25.6 MB
__device__ float g_agg2[(size_t)NN * HH];   // mean(h[nbrs])      25.6 MB
__device__ int   g_cnt[NN];
__device__ int   g_rowptr[NN];
__device__ int   g_cur[NN];
__device__ float g_invdeg[NN];
__device__ int   g_srcs[2000000];
__device__ int   g_exc[NB * 256];
__device__ int   g_bsum[512];
__device__ int   g_is64;

// ---- f32x2 packed-math helpers (sm_103a FFMA2) ----
__device__ __forceinline__ u64 pack2(float lo, float hi) {
    u64 r;
    asm("mov.b64 %0, {%1, %2};" : "=l"(r) : "f"(lo), "f"(hi));
    return r;
}
__device__ __forceinline__ void unpack2(u64 v, float& lo, float& hi) {
    asm("mov.b64 {%0, %1}, %2;" : "=f"(lo), "=f"(hi) : "l"(v));
}
__device__ __forceinline__ void fma2(u64& d, u64 a, u64 b) {
    asm("fma.rn.f32x2 %0, %1, %2, %0;" : "+l"(d) : "l"(a), "l"(b));
}

// ---------------------------------------------------------------------------
// detzero: zero g_cnt; block 0 detects int64 vs int32 edge dtype in parallel.
// ---------------------------------------------------------------------------
__global__ void k_detzero(const void* __restrict__ ei) {
    int i = blockIdx.x * blockDim.x + threadIdx.x;
    if (i < NN) g_cnt[i] = 0;
    if (blockIdx.x == 0) {
        if (threadIdx.x == 0) g_is64 = 1;
        __syncthreads();
        if (threadIdx.x < 128) {
            long long v = ((const long long*)ei)[threadIdx.x];
            if (v < 0 || v >= NN) atomicAnd(&g_is64, 0);
        }
    }
}

__global__ void k_hist(const void* __restrict__ ei, int nE) {
    int e = blockIdx.x * blockDim.x + threadIdx.x;
    if (e >= nE) return;
    int d = g_is64 ? (int)((const long long*)ei)[nE + e]
                   : ((const int*)ei)[nE + e];
    atomicAdd(&g_cnt[d], 1);
}

__global__ void k_scan1() {
    __shared__ int sh[256];
    int t = threadIdx.x, b = blockIdx.x;
    int i = b * 256 + t;
    int v = (i < NN) ? g_cnt[i] : 0;
    sh[t] = v;
    __syncthreads();
    #pragma unroll
    for (int off = 1; off < 256; off <<= 1) {
        int u = (t >= off) ? sh[t - off] : 0;
        __syncthreads();
        sh[t] += u;
        __syncthreads();
    }
    if (i < NN) g_exc[i] = sh[t] - v;
    if (t == 255) g_bsum[b] = sh[t];
}

__global__ void k_scan23() {
    __shared__ int red[8];
    __shared__ int boff;
    int b = blockIdx.x, t = threadIdx.x;
    int v = 0;
    if (t < b) v = g_bsum[t];
    if (t + 256 < b) v += g_bsum[t + 256];
    #pragma unroll
    for (int o = 16; o; o >>= 1) v += __shfl_xor_sync(0xffffffffu, v, o);
    if ((t & 31) == 0) red[t >> 5] = v;
    __syncthreads();
    if (t == 0) {
        int s = 0;
        #pragma unroll
        for (int j = 0; j < 8; ++j) s += red[j];
        boff = s;
    }
    __syncthreads();
    int i = b * 256 + t;
    if (i < NN) {
        int row = g_exc[i] + boff;
        g_rowptr[i] = row;
        g_cur[i] = row;
        g_invdeg[i] = 1.0f / fmaxf((float)g_cnt[i], 1.0f);
    }
}

__global__ void k_fill(const void* __restrict__ ei, int nE) {
    int e = blockIdx.x * blockDim.x + threadIdx.x;
    if (e >= nE) return;
    int s, d;
    if (g_is64) {
        const long long* p = (const long long*)ei;
        s = (int)p[e]; d = (int)p[nE + e];
    } else {
        const int* p = (const int*)ei;
        s = p[e]; d = p[nE + e];
    }
    int pos = atomicAdd(&g_cur[d], 1);
    g_srcs[pos] = s;
}

// ---------------------------------------------------------------------------
// GEMM1: [y1 | self+b1] = x[N,128] @ [W1l | W1r][128,128]
// 64x128 tile, 256 threads, 4x8 microtile in packed f32x2 FMA.
// __launch_bounds__(256,4): cap regs at 64 -> 4 blocks/SM (occupancy fix).
// B read as 2x LDS.128 (ulonglong2) per k-step.
// ---------------------------------------------------------------------------
__global__ void __launch_bounds__(256, 4)
k_gemm1(const float* __restrict__ x,
        const float* __restrict__ Wl,
        const float* __restrict__ Wr,
        const float* __restrict__ b) {
    __shared__ float As[32][65];
    __shared__ float Bs[32][128];

    int tid = threadIdx.x;
    int tx = tid & 15;
    int ty = tid >> 4;
    int m0 = blockIdx.x * 64;

    u64 acc[4][4] = {};

    #pragma unroll 1
    for (int c = 0; c < 4; ++c) {
        int kb = c * 32;
        __syncthreads();
        {
            int kk = (tid & 7) * 4;
            int m  = tid >> 3;
            #pragma unroll
            for (int r = 0; r < 2; ++r, m += 32) {
                int mg = min(m0 + m, NN - 1);
                float4 v = __ldg((const float4*)(x + (size_t)mg * DD + kb + kk));
                As[kk + 0][m] = v.x;
                As[kk + 1][m] = v.y;
                As[kk + 2][m] = v.z;
                As[kk + 3][m] = v.w;
            }
        }
        {
            int k = tid >> 3;
            int n = (tid & 7) * 16;
            const float* W = (n < 64) ? (Wl + (size_t)(kb + k) * 64 + n)
                                      : (Wr + (size_t)(kb + k) * 64 + (n - 64));
            float4 v0 = __ldg((const float4*)(W));
            float4 v1 = __ldg((const float4*)(W + 4));
            float4 v2 = __ldg((const float4*)(W + 8));
            float4 v3 = __ldg((const float4*)(W + 12));
            *(float4*)&Bs[k][n]      = v0;
            *(float4*)&Bs[k][n + 4]  = v1;
            *(float4*)&Bs[k][n + 8]  = v2;
            *(float4*)&Bs[k][n + 12] = v3;
        }
        __syncthreads();
        #pragma unroll
        for (int k = 0; k < 32; ++k) {
            u64 A2[4];
            #pragma unroll
            for (int i = 0; i < 4; ++i) {
                float a = As[k][ty * 4 + i];
                A2[i] = pack2(a, a);
            }
            // 2x LDS.128 for B (32B aligned: k*512 + tx*32 bytes)
            ulonglong2 bq0 = *(const ulonglong2*)&Bs[k][tx * 8];
            ulonglong2 bq1 = *(const ulonglong2*)&Bs[k][tx * 8 + 4];
            u64 B0 = bq0.x, B1 = bq0.y, B2 = bq1.x, B3 = bq1.y;
            #pragma unroll
            for (int i = 0; i < 4; ++i) {
                fma2(acc[i][0], A2[i], B0);
                fma2(acc[i][1], A2[i], B1);
                fma2(acc[i][2], A2[i], B2);
                fma2(acc[i][3], A2[i], B3);
            }
        }
    }

    int n = tx * 8;
    bool isSelf = (n >= 64);
    float bb[8];
    #pragma unroll
    for (int j = 0; j < 8; ++j) bb[j] = isSelf ? b[n - 64 + j] : 0.f;
    float* dst = isSelf ? g_self : g_y1;
    int nc = isSelf ? (n - 64) : n;
    #pragma unroll
    for (int i = 0; i < 4; ++i) {
        int mg = m0 + ty * 4 + i;
        if (mg < NN) {
            float o[8];
            #pragma unroll
            for (int j = 0; j < 4; ++j) unpack2(acc[i][j], o[2 * j], o[2 * j + 1]);
            float4 o0, o1;
            o0.x = o[0] + bb[0]; o0.y = o[1] + bb[1];
            o0.z = o[2] + bb[2]; o0.w = o[3] + bb[3];
            o1.x = o[4] + bb[4]; o1.y = o[5] + bb[5];
            o1.z = o[6] + bb[6]; o1.w = o[7] + bb[7];
            *(float4*)(dst + (size_t)mg * HH + nc)     = o0;
            *(float4*)(dst + (size_t)mg * HH + nc + 4) = o1;
        }
    }
}

// ---------------------------------------------------------------------------
// agg1 + ReLU: h[n] = relu( invdeg * sum_{s} y1[s] + self[n] )
// ---------------------------------------------------------------------------
__global__ void k_agg1(void) {
    int w = (blockIdx.x * blockDim.x + threadIdx.x) >> 5;
    int lane = threadIdx.x & 31;
    if (w >= NN) return;
    int beg = g_rowptr[w], n = g_cnt[w];
    const float2* yb = (const float2*)g_y1;
    float2 a0 = make_float2(0.f, 0.f), a1 = make_float2(0.f, 0.f);
    int e = 0;
    for (; e + 1 < n; e += 2) {
        int s0 = g_srcs[beg + e];
        int s1 = g_srcs[beg + e + 1];
        float2 v0 = __ldg(yb + (size_t)s0 * 32 + lane);
        float2 v1 = __ldg(yb + (size_t)s1 * 32 + lane);
        a0.x += v0.x; a0.y += v0.y;
        a1.x += v1.x; a1.y += v1.y;
    }
    if (e < n) {
        int s0 = g_srcs[beg + e];
        float2 v0 = __ldg(yb + (size_t)s0 * 32 + lane);
        a0.x += v0.x; a0.y += v0.y;
    }
    float sc = g_invdeg[w];
    float2 s = ((const float2*)g_self)[(size_t)w * 32 + lane];
    float2 o;
    o.x = fmaxf((a0.x + a1.x) * sc + s.x, 0.f);
    o.y = fmaxf((a0.y + a1.y) * sc + s.y, 0.f);
    ((float2*)g_h)[(size_t)w * 32 + lane] = o;
}

// ---------------------------------------------------------------------------
// agg2: g_agg2[n] = invdeg * sum_{s} h[s]
// ---------------------------------------------------------------------------
__global__ void k_agg2(void) {
    int w = (blockIdx.x * blockDim.x + threadIdx.x) >> 5;
    int lane = threadIdx.x & 31;
    if (w >= NN) return;
    int beg = g_rowptr[w], n = g_cnt[w];
    const float2* hb = (const float2*)g_h;
    float2 a0 = make_float2(0.f, 0.f), a1 = make_float2(0.f, 0.f);
    int e = 0;
    for (; e + 1 < n; e += 2) {
        int s0 = g_srcs[beg + e];
        int s1 = g_srcs[beg + e + 1];
        float2 v0 = __ldg(hb + (size_t)s0 * 32 + lane);
        float2 v1 = __ldg(hb + (size_t)s1 * 32 + lane);
        a0.x += v0.x; a0.y += v0.y;
        a1.x += v1.x; a1.y += v1.y;
    }
    if (e < n) {
        int s0 = g_srcs[beg + e];
        float2 v0 = __ldg(hb + (size_t)s0 * 32 + lane);
        a0.x += v0.x; a0.y += v0.y;
    }
    float sc = g_invdeg[w];
    float2 o;
    o.x = (a0.x + a1.x) * sc;
    o.y = (a0.y + a1.y) * sc;
    ((float2*)g_agg2)[(size_t)w * 32 + lane] = o;
}

// ---------------------------------------------------------------------------
// GEMM2 + fused log_softmax (warp per node), packed f32x2.
// ---------------------------------------------------------------------------
__global__ void k_gemm2(const float* __restrict__ Wl,
                        const float* __restrict__ Wr,
                        const float* __restrict__ b,
                        float* __restrict__ out) {
    __shared__ float2 sW[64 * 40];
    __shared__ float sb[40];
    int tid = threadIdx.x;
    for (int i = tid; i < 64 * 40; i += blockDim.x)
        sW[i] = make_float2(Wl[i], Wr[i]);
    if (tid < 40) sb[tid] = b[tid];
    __syncthreads();

    int w = (blockIdx.x * blockDim.x + tid) >> 5;
    int lane = tid & 31;
    if (w >= NN) return;
    bool lo8 = (lane < 8);

    const float* ag = g_agg2 + (size_t)w * HH;
    const float* hr = g_h    + (size_t)w * HH;
    float a0 = ag[lane], a1 = ag[lane + 32];
    float h0 = hr[lane], h1 = hr[lane + 32];

    u64 acc0 = 0, acc1 = 0;
    #pragma unroll
    for (int k = 0; k < 32; ++k) {
        float av = __shfl_sync(0xffffffffu, a0, k);
        float hv = __shfl_sync(0xffffffffu, h0, k);
        u64 p = pack2(av, hv);
        fma2(acc0, p, *(const u64*)&sW[k * 40 + lane]);
        if (lo8) fma2(acc1, p, *(const u64*)&sW[k * 40 + 32 + lane]);
    }
    #pragma unroll
    for (int k = 0; k < 32; ++k) {
        float av = __shfl_sync(0xffffffffu, a1, k);
        float hv = __shfl_sync(0xffffffffu, h1, k);
        u64 p = pack2(av, hv);
        int kr = k + 32;
        fma2(acc0, p, *(const u64*)&sW[kr * 40 + lane]);
        if (lo8) fma2(acc1, p, *(const u64*)&sW[kr * 40 + 32 + lane]);
    }

    float u0, v0, u1, v1;
    unpack2(acc0, u0, v0);
    unpack2(acc1, u1, v1);
    float z0 = u0 + v0 + sb[lane];
    float z1 = lo8 ? (u1 + v1 + sb[32 + lane]) : -INFINITY;

    float m = fmaxf(z0, z1);
    #pragma unroll
    for (int o = 16; o; o >>= 1) m = fmaxf(m, __shfl_xor_sync(0xffffffffu, m, o));
    float e = expf(z0 - m) + (lo8 ? expf(z1 - m) : 0.f);
    #pragma unroll
    for (int o = 16; o; o >>= 1) e += __shfl_xor_sync(0xffffffffu, e, o);
    float lse = logf(e) + m;

    out[(size_t)w * CC + lane] = z0 - lse;
    if (lo8) out[(size_t)w * CC + 32 + lane] = z1 - lse;
}

// ---------------------------------------------------------------------------
extern "C" void kernel_launch(void* const* d_in, const int* in_sizes, int n_in,
                              void* d_out, int out_size) {
    const float* x   = (const float*)d_in[0];
    const void*  ei  = d_in[1];
    const float* W1l = (const float*)d_in[2];
    const float* W1r = (const float*)d_in[3];
    const float* b1  = (const float*)d_in[4];
    const float* W2l = (const float*)d_in[5];
    const float* W2r = (const float*)d_in[6];
    const float* b2  = (const float*)d_in[7];
    float* out = (float*)d_out;

    int nE = in_sizes[1] / 2;
    int eBlocks = (nE + 255) / 256;
    int nWarpBlocks = (NN * 32 + 255) / 256;

    k_detzero<<<(NN + 255) / 256, 256>>>(ei);          // 1
    k_hist<<<eBlocks, 256>>>(ei, nE);                  // 2
    k_scan1<<<NB, 256>>>();                            // 3
    k_gemm1<<<(NN + 63) / 64, 256>>>(x, W1l, W1r, b1); // 4 <- ncu window
    k_scan23<<<NB, 256>>>();                           // 5
    k_fill<<<eBlocks, 256>>>(ei, nE);                  // 6
    k_agg1<<<nWarpBlocks, 256>>>();                    // 7
    k_agg2<<<nWarpBlocks, 256>>>();                    // 8
    k_gemm2<<<(NN + 7) / 8, 256>>>(W2l, W2r, b2, out); // 9
}

// round 9
// speedup vs baseline: 1.1663x; 1.1069x over previous
#include <cuda_runtime.h>
#include <math.h>

#define NN 100000
#define DD 128
#define HH 64
#define CC 40
#define NB 391          // ceil(NN/256) scan blocks

typedef unsigned long long u64;

// ---- scratch (__device__ globals per harness rules) ----
__device__ float g_y1[(size_t)NN * HH];     // x @ W1l            25.6 MB
__device__ float g_self[(size_t)NN * HH];   // x @ W1r + b1       25.6 MB
__device__ float g_h[(size_t)NN * HH];      // layer-1 output     25.6 MB
__device__ float g_agg2[(size_t)NN * HH];   // mean(h[nbrs])      25.6 MB
__device__ int   g_cnt[NN];
__device__ int   g_rowptr[NN];
__device__ int   g_cur[NN];
__device__ float g_invdeg[NN];
__device__ int   g_srcs[2000000];
__device__ int   g_exc[NB * 256];
__device__ int   g_bsum[512];
__device__ int   g_is64;

// ---- f32x2 packed-math helpers (sm_103a FFMA2) ----
__device__ __forceinline__ u64 pack2(float lo, float hi) {
    u64 r;
    asm("mov.b64 %0, {%1, %2};" : "=l"(r) : "f"(lo), "f"(hi));
    return r;
}
__device__ __forceinline__ void unpack2(u64 v, float& lo, float& hi) {
    asm("mov.b64 {%0, %1}, %2;" : "=f"(lo), "=f"(hi) : "l"(v));
}
__device__ __forceinline__ void fma2(u64& d, u64 a, u64 b) {
    asm("fma.rn.f32x2 %0, %1, %2, %0;" : "+l"(d) : "l"(a), "l"(b));
}

// ---------------------------------------------------------------------------
__global__ void k_detzero(const void* __restrict__ ei) {
    int i = blockIdx.x * blockDim.x + threadIdx.x;
    if (i < NN) g_cnt[i] = 0;
    if (blockIdx.x == 0) {
        if (threadIdx.x == 0) g_is64 = 1;
        __syncthreads();
        if (threadIdx.x < 128) {
            long long v = ((const long long*)ei)[threadIdx.x];
            if (v < 0 || v >= NN) atomicAnd(&g_is64, 0);
        }
    }
}

__global__ void k_hist(const void* __restrict__ ei, int nE) {
    int e = blockIdx.x * blockDim.x + threadIdx.x;
    if (e >= nE) return;
    int d = g_is64 ? (int)((const long long*)ei)[nE + e]
                   : ((const int*)ei)[nE + e];
    atomicAdd(&g_cnt[d], 1);
}

__global__ void k_scan1() {
    __shared__ int sh[256];
    int t = threadIdx.x, b = blockIdx.x;
    int i = b * 256 + t;
    int v = (i < NN) ? g_cnt[i] : 0;
    sh[t] = v;
    __syncthreads();
    #pragma unroll
    for (int off = 1; off < 256; off <<= 1) {
        int u = (t >= off) ? sh[t - off] : 0;
        __syncthreads();
        sh[t] += u;
        __syncthreads();
    }
    if (i < NN) g_exc[i] = sh[t] - v;
    if (t == 255) g_bsum[b] = sh[t];
}

__global__ void k_scan23() {
    __shared__ int red[8];
    __shared__ int boff;
    int b = blockIdx.x, t = threadIdx.x;
    int v = 0;
    if (t < b) v = g_bsum[t];
    if (t + 256 < b) v += g_bsum[t + 256];
    #pragma unroll
    for (int o = 16; o; o >>= 1) v += __shfl_xor_sync(0xffffffffu, v, o);
    if ((t & 31) == 0) red[t >> 5] = v;
    __syncthreads();
    if (t == 0) {
        int s = 0;
        #pragma unroll
        for (int j = 0; j < 8; ++j) s += red[j];
        boff = s;
    }
    __syncthreads();
    int i = b * 256 + t;
    if (i < NN) {
        int row = g_exc[i] + boff;
        g_rowptr[i] = row;
        g_cur[i] = row;
        g_invdeg[i] = 1.0f / fmaxf((float)g_cnt[i], 1.0f);
    }
}

__global__ void k_fill(const void* __restrict__ ei, int nE) {
    int e = blockIdx.x * blockDim.x + threadIdx.x;
    if (e >= nE) return;
    int s, d;
    if (g_is64) {
        const long long* p = (const long long*)ei;
        s = (int)p[e]; d = (int)p[nE + e];
    } else {
        const int* p = (const int*)ei;
        s = p[e]; d = p[nE + e];
    }
    int pos = atomicAdd(&g_cur[d], 1);
    g_srcs[pos] = s;
}

// ---------------------------------------------------------------------------
// GEMM1 v3: [y1 | self+b1] = x[N,128] @ [W1l | W1r][128,128]
// 128x128 tile, 256 threads, 8x8 microtile. f32x2 pairs TWO M-ROWS per lane:
//   acc[i][j] = ( row(ty*8+2i) , row(ty*8+2i+1) ) for col j*16+tx.
// A: smem [k][m] pitch 130, read as aligned LDS.64 row-pairs (no packing).
// B: pre-duplicated (b,b) u64 in smem, conflict-free LDS.64 (col = j*16+tx).
// Inner loop per k: 4 LDS.64(A) + 8 LDS.64(B) + 32 FFMA2 (=128 MACs).
// ---------------------------------------------------------------------------
__global__ void __launch_bounds__(256, 2)
k_gemm1(const float* __restrict__ x,
        const float* __restrict__ Wl,
        const float* __restrict__ Wr,
        const float* __restrict__ b) {
    __shared__ float As[16][130];     // [k][m], pitch 130: 8B-aligned u64 reads
    __shared__ u64   Bs2[16][128];    // duplicated (b,b) pairs

    int tid = threadIdx.x;
    int tx = tid & 15;        // col lane: cols {tx, tx+16, ..., tx+112}
    int ty = tid >> 4;        // row group: rows ty*8 .. ty*8+7
    int m0 = blockIdx.x * 128;

    u64 acc[4][8] = {};       // [rowpair][col j]

    #pragma unroll 1
    for (int c = 0; c < 8; ++c) {
        int kb = c * 16;
        __syncthreads();
        // load A: 128 rows x 16 k ; thread: 2 rows x 4 k
        {
            int m  = tid >> 2;             // 0..63
            int kk = (tid & 3) * 4;        // 0,4,8,12
            #pragma unroll
            for (int r = 0; r < 2; ++r, m += 64) {
                int mg = min(m0 + m, NN - 1);
                float4 v = __ldg((const float4*)(x + (size_t)mg * DD + kb + kk));
                As[kk + 0][m] = v.x;
                As[kk + 1][m] = v.y;
                As[kk + 2][m] = v.z;
                As[kk + 3][m] = v.w;
            }
        }
        // load B: 16 k-rows x 128 cols, duplicated into u64 pairs
        {
            int k = tid >> 4;              // 0..15
            int n = (tid & 15) * 8;        // 0..120
            const float* W = (n < 64) ? (Wl + (size_t)(kb + k) * 64 + n)
                                      : (Wr + (size_t)(kb + k) * 64 + (n - 64));
            float4 v0 = __ldg((const float4*)(W));
            float4 v1 = __ldg((const float4*)(W + 4));
            Bs2[k][n + 0] = pack2(v0.x, v0.x);
            Bs2[k][n + 1] = pack2(v0.y, v0.y);
            Bs2[k][n + 2] = pack2(v0.z, v0.z);
            Bs2[k][n + 3] = pack2(v0.w, v0.w);
            Bs2[k][n + 4] = pack2(v1.x, v1.x);
            Bs2[k][n + 5] = pack2(v1.y, v1.y);
            Bs2[k][n + 6] = pack2(v1.z, v1.z);
            Bs2[k][n + 7] = pack2(v1.w, v1.w);
        }
        __syncthreads();
        #pragma unroll
        for (int k = 0; k < 16; ++k) {
            u64 Ap[4];
            #pragma unroll
            for (int i = 0; i < 4; ++i)
                Ap[i] = *(const u64*)&As[k][ty * 8 + 2 * i];
            #pragma unroll
            for (int j = 0; j < 8; ++j) {
                u64 Bv = Bs2[k][j * 16 + tx];
                fma2(acc[0][j], Ap[0], Bv);
                fma2(acc[1][j], Ap[1], Bv);
                fma2(acc[2][j], Ap[2], Bv);
                fma2(acc[3][j], Ap[3], Bv);
            }
        }
    }

    // epilogue: col<64 -> g_y1 ; col>=64 -> g_self (+b1). Scalar coalesced STG.
    #pragma unroll
    for (int j = 0; j < 8; ++j) {
        int col = j * 16 + tx;
        bool isSelf = (col >= 64);
        int nc = isSelf ? (col - 64) : col;
        float bb = isSelf ? b[nc] : 0.f;
        float* dst = isSelf ? g_self : g_y1;
        #pragma unroll
        for (int i = 0; i < 4; ++i) {
            float v0, v1;
            unpack2(acc[i][j], v0, v1);
            int r0 = m0 + ty * 8 + 2 * i;
            if (r0 < NN)     dst[(size_t)r0 * HH + nc]       = v0 + bb;
            if (r0 + 1 < NN) dst[(size_t)(r0 + 1) * HH + nc] = v1 + bb;
        }
    }
}

// ---------------------------------------------------------------------------
// agg1 + ReLU: h[n] = relu( invdeg * sum_{s} y1[s] + self[n] )
// ---------------------------------------------------------------------------
__global__ void k_agg1(void) {
    int w = (blockIdx.x * blockDim.x + threadIdx.x) >> 5;
    int lane = threadIdx.x & 31;
    if (w >= NN) return;
    int beg = g_rowptr[w], n = g_cnt[w];
    const float2* yb = (const float2*)g_y1;
    float2 a0 = make_float2(0.f, 0.f), a1 = make_float2(0.f, 0.f);
    int e = 0;
    for (; e + 1 < n; e += 2) {
        int s0 = g_srcs[beg + e];
        int s1 = g_srcs[beg + e + 1];
        float2 v0 = __ldg(yb + (size_t)s0 * 32 + lane);
        float2 v1 = __ldg(yb + (size_t)s1 * 32 + lane);
        a0.x += v0.x; a0.y += v0.y;
        a1.x += v1.x; a1.y += v1.y;
    }
    if (e < n) {
        int s0 = g_srcs[beg + e];
        float2 v0 = __ldg(yb + (size_t)s0 * 32 + lane);
        a0.x += v0.x; a0.y += v0.y;
    }
    float sc = g_invdeg[w];
    float2 s = ((const float2*)g_self)[(size_t)w * 32 + lane];
    float2 o;
    o.x = fmaxf((a0.x + a1.x) * sc + s.x, 0.f);
    o.y = fmaxf((a0.y + a1.y) * sc + s.y, 0.f);
    ((float2*)g_h)[(size_t)w * 32 + lane] = o;
}

// ---------------------------------------------------------------------------
// agg2: g_agg2[n] = invdeg * sum_{s} h[s]
// ---------------------------------------------------------------------------
__global__ void k_agg2(void) {
    int w = (blockIdx.x * blockDim.x + threadIdx.x) >> 5;
    int lane = threadIdx.x & 31;
    if (w >= NN) return;
    int beg = g_rowptr[w], n = g_cnt[w];
    const float2* hb = (const float2*)g_h;
    float2 a0 = make_float2(0.f, 0.f), a1 = make_float2(0.f, 0.f);
    int e = 0;
    for (; e + 1 < n; e += 2) {
        int s0 = g_srcs[beg + e];
        int s1 = g_srcs[beg + e + 1];
        float2 v0 = __ldg(hb + (size_t)s0 * 32 + lane);
        float2 v1 = __ldg(hb + (size_t)s1 * 32 + lane);
        a0.x += v0.x; a0.y += v0.y;
        a1.x += v1.x; a1.y += v1.y;
    }
    if (e < n) {
        int s0 = g_srcs[beg + e];
        float2 v0 = __ldg(hb + (size_t)s0 * 32 + lane);
        a0.x += v0.x; a0.y += v0.y;
    }
    float sc = g_invdeg[w];
    float2 o;
    o.x = (a0.x + a1.x) * sc;
    o.y = (a0.y + a1.y) * sc;
    ((float2*)g_agg2)[(size_t)w * 32 + lane] = o;
}

// ---------------------------------------------------------------------------
// GEMM2 + fused log_softmax (warp per node), packed f32x2.
// ---------------------------------------------------------------------------
__global__ void k_gemm2(const float* __restrict__ Wl,
                        const float* __restrict__ Wr,
                        const float* __restrict__ b,
                        float* __restrict__ out) {
    __shared__ float2 sW[64 * 40];
    __shared__ float sb[40];
    int tid = threadIdx.x;
    for (int i = tid; i < 64 * 40; i += blockDim.x)
        sW[i] = make_float2(Wl[i], Wr[i]);
    if (tid < 40) sb[tid] = b[tid];
    __syncthreads();

    int w = (blockIdx.x * blockDim.x + tid) >> 5;
    int lane = tid & 31;
    if (w >= NN) return;
    bool lo8 = (lane < 8);

    const float* ag = g_agg2 + (size_t)w * HH;
    const float* hr = g_h    + (size_t)w * HH;
    float a0 = ag[lane], a1 = ag[lane + 32];
    float h0 = hr[lane], h1 = hr[lane + 32];

    u64 acc0 = 0, acc1 = 0;
    #pragma unroll
    for (int k = 0; k < 32; ++k) {
        float av = __shfl_sync(0xffffffffu, a0, k);
        float hv = __shfl_sync(0xffffffffu, h0, k);
        u64 p = pack2(av, hv);
        fma2(acc0, p, *(const u64*)&sW[k * 40 + lane]);
        if (lo8) fma2(acc1, p, *(const u64*)&sW[k * 40 + 32 + lane]);
    }
    #pragma unroll
    for (int k = 0; k < 32; ++k) {
        float av = __shfl_sync(0xffffffffu, a1, k);
        float hv = __shfl_sync(0xffffffffu, h1, k);
        u64 p = pack2(av, hv);
        int kr = k + 32;
        fma2(acc0, p, *(const u64*)&sW[kr * 40 + lane]);
        if (lo8) fma2(acc1, p, *(const u64*)&sW[kr * 40 + 32 + lane]);
    }

    float u0, v0, u1, v1;
    unpack2(acc0, u0, v0);
    unpack2(acc1, u1, v1);
    float z0 = u0 + v0 + sb[lane];
    float z1 = lo8 ? (u1 + v1 + sb[32 + lane]) : -INFINITY;

    float m = fmaxf(z0, z1);
    #pragma unroll
    for (int o = 16; o; o >>= 1) m = fmaxf(m, __shfl_xor_sync(0xffffffffu, m, o));
    float e = expf(z0 - m) + (lo8 ? expf(z1 - m) : 0.f);
    #pragma unroll
    for (int o = 16; o; o >>= 1) e += __shfl_xor_sync(0xffffffffu, e, o);
    float lse = logf(e) + m;

    out[(size_t)w * CC + lane] = z0 - lse;
    if (lo8) out[(size_t)w * CC + 32 + lane] = z1 - lse;
}

// ---------------------------------------------------------------------------
extern "C" void kernel_launch(void* const* d_in, const int* in_sizes, int n_in,
                              void* d_out, int out_size) {
    const float* x   = (const float*)d_in[0];
    const void*  ei  = d_in[1];
    const float* W1l = (const float*)d_in[2];
    const float* W1r = (const float*)d_in[3];
    const float* b1  = (const float*)d_in[4];
    const float* W2l = (const float*)d_in[5];
    const float* W2r = (const float*)d_in[6];
    const float* b2  = (const float*)d_in[7];
    float* out = (float*)d_out;

    int nE = in_sizes[1] / 2;
    int eBlocks = (nE + 255) / 256;
    int nWarpBlocks = (NN * 32 + 255) / 256;

    k_detzero<<<(NN + 255) / 256, 256>>>(ei);            // 1
    k_hist<<<eBlocks, 256>>>(ei, nE);                    // 2
    k_scan1<<<NB, 256>>>();                              // 3
    k_gemm1<<<(NN + 127) / 128, 256>>>(x, W1l, W1r, b1); // 4 <- ncu window
    k_scan23<<<NB, 256>>>();                             // 5
    k_fill<<<eBlocks, 256>>>(ei, nE);                    // 6
    k_agg1<<<nWarpBlocks, 256>>>();                      // 7
    k_agg2<<<nWarpBlocks, 256>>>();                      // 8
    k_gemm2<<<(NN + 7) / 8, 256>>>(W2l, W2r, b2, out);   // 9
}